// round 2
// baseline (speedup 1.0000x reference)
#include <cuda_runtime.h>

// Problem shape (fixed by the dataset):
//   z:      (4096, 1, 64, 128) f32  -> row of 8192 floats per batch entry
//   ch_ids: (4096,) int32 or int64, values in [0, 32)
//   out:    (4096, 128, 128) f32    -> row of 16384 floats; first 8192 = z row,
//                                      last 8192 = per-channel mean row
#define BATCH   4096
#define NCH     32
#define ZROW    8192        // 64*128 floats
#define OROW    16384       // 128*128 floats
#define CHUNK   512         // floats handled per block (128 threads * float4)
#define NCHUNK  (ZROW / CHUNK)   // 16

// Scratch (no allocations allowed): per-channel ordered row lists + counts.
__device__ int g_list[NCH * BATCH];   // 512 KB
__device__ int g_counts[NCH];

// ---------------------------------------------------------------------------
// Kernel 1: build per-channel ordered row-index lists. One block, 32 warps;
// warp w owns channel w. Deterministic (no atomics, stable b order).
//
// dtype probe: ch_ids may be int32 (JAX x64 disabled) or int64. Interpret as
// int32[]; if the first 64 odd words are all zero, it's int64 (values < 32 so
// the high word is 0). P(false positive on random int32 in [0,32)) = 32^-64.
// ---------------------------------------------------------------------------
__global__ void __launch_bounds__(1024, 1)
build_lists_kernel(const int* __restrict__ ids32) {
    __shared__ int s_stride;   // 1 for int32, 2 for int64
    if (threadIdx.x == 0) {
        int nz = 0;
        #pragma unroll
        for (int i = 0; i < 64; ++i) nz += (ids32[2 * i + 1] != 0);
        s_stride = (nz == 0) ? 2 : 1;
    }
    __syncthreads();
    const int stride = s_stride;

    const int w    = threadIdx.x >> 5;   // channel this warp owns
    const int lane = threadIdx.x & 31;
    int count = 0;
    for (int base = 0; base < BATCH; base += 32) {
        const int id = ids32[(base + lane) * stride];
        const unsigned mask = __ballot_sync(0xffffffffu, id == w);
        if (id == w) {
            const int pos = count + __popc(mask & ((1u << lane) - 1u));
            g_list[w * BATCH + pos] = base + lane;
        }
        count += __popc(mask);
    }
    if (lane == 0) g_counts[w] = count;
}

// ---------------------------------------------------------------------------
// Kernel 2: fused copy + per-channel mean + scatter.
// grid = (NCHUNK, NCH), block = 128 threads. Block (chunk, c):
//   pass 1: for each row b of channel c: load z slice (float4/thread),
//           accumulate, and write the top-half copy of out.
//   pass 2: mean = acc / max(cnt,1); write bottom-half slice for every row b.
// ---------------------------------------------------------------------------
__global__ void __launch_bounds__(128)
mix_kernel(const float* __restrict__ z, float* __restrict__ out) {
    __shared__ int rows[BATCH];          // 16 KB (worst case all rows one channel)

    const int c     = blockIdx.y;
    const int chunk = blockIdx.x;
    const int tid   = threadIdx.x;

    const int cnt = g_counts[c];
    for (int i = tid; i < cnt; i += 128) rows[i] = g_list[c * BATCH + i];
    __syncthreads();

    const int off = chunk * CHUNK + tid * 4;   // float offset within a z row

    float4 acc = make_float4(0.f, 0.f, 0.f, 0.f);

    int i = 0;
    for (; i + 4 <= cnt; i += 4) {
        const int b0 = rows[i + 0];
        const int b1 = rows[i + 1];
        const int b2 = rows[i + 2];
        const int b3 = rows[i + 3];
        const float4 v0 = *(const float4*)(z + (size_t)b0 * ZROW + off);
        const float4 v1 = *(const float4*)(z + (size_t)b1 * ZROW + off);
        const float4 v2 = *(const float4*)(z + (size_t)b2 * ZROW + off);
        const float4 v3 = *(const float4*)(z + (size_t)b3 * ZROW + off);
        *(float4*)(out + (size_t)b0 * OROW + off) = v0;
        *(float4*)(out + (size_t)b1 * OROW + off) = v1;
        *(float4*)(out + (size_t)b2 * OROW + off) = v2;
        *(float4*)(out + (size_t)b3 * OROW + off) = v3;
        // pairwise-ish accumulate
        acc.x += (v0.x + v1.x) + (v2.x + v3.x);
        acc.y += (v0.y + v1.y) + (v2.y + v3.y);
        acc.z += (v0.z + v1.z) + (v2.z + v3.z);
        acc.w += (v0.w + v1.w) + (v2.w + v3.w);
    }
    for (; i < cnt; ++i) {
        const int b = rows[i];
        const float4 v = *(const float4*)(z + (size_t)b * ZROW + off);
        *(float4*)(out + (size_t)b * OROW + off) = v;
        acc.x += v.x; acc.y += v.y; acc.z += v.z; acc.w += v.w;
    }

    const float inv = 1.0f / (float)(cnt > 0 ? cnt : 1);
    float4 m;
    m.x = acc.x * inv; m.y = acc.y * inv; m.z = acc.z * inv; m.w = acc.w * inv;

    // pass 2: broadcast the mean slice to the bottom half of every row of c
    int j = 0;
    for (; j + 4 <= cnt; j += 4) {
        const int b0 = rows[j + 0];
        const int b1 = rows[j + 1];
        const int b2 = rows[j + 2];
        const int b3 = rows[j + 3];
        *(float4*)(out + (size_t)b0 * OROW + ZROW + off) = m;
        *(float4*)(out + (size_t)b1 * OROW + ZROW + off) = m;
        *(float4*)(out + (size_t)b2 * OROW + ZROW + off) = m;
        *(float4*)(out + (size_t)b3 * OROW + ZROW + off) = m;
    }
    for (; j < cnt; ++j) {
        const int b = rows[j];
        *(float4*)(out + (size_t)b * OROW + ZROW + off) = m;
    }
}

extern "C" void kernel_launch(void* const* d_in, const int* in_sizes, int n_in,
                              void* d_out, int out_size) {
    const float* z   = (const float*)d_in[0];
    const int*   ids = (const int*)d_in[1];
    float*       out = (float*)d_out;

    build_lists_kernel<<<1, 1024>>>(ids);

    dim3 grid(NCHUNK, NCH);
    mix_kernel<<<grid, 128>>>(z, out);
}

// round 3
// speedup vs baseline: 1.1696x; 1.1696x over previous
#include <cuda_runtime.h>

// Problem shape (fixed by the dataset):
//   z:      (4096, 1, 64, 128) f32  -> row of 8192 floats per batch entry
//   ch_ids: (4096,) int32 or int64, values in [0, 32)
//   out:    (4096, 128, 128) f32    -> first 8192 = z row, last 8192 = channel mean
#define BATCH   4096
#define NCH     32
#define ZROW    8192
#define OROW    16384
#define CHUNK   512                    // floats per block slice (128 thr * float4)
#define NCHUNK  (ZROW / CHUNK)         // 16
#define SPLIT   4                      // row-list split factor per channel
#define MAXROWS (BATCH / SPLIT)        // worst-case rows per split... (see note)

// NOTE: worst case one channel owns all 4096 rows -> a split owns 1024 rows.
// Scratch (no allocations allowed):
__device__ int   g_list[NCH * BATCH];            // 512 KB, per-channel ordered rows
__device__ int   g_counts[NCH];
__device__ float g_partial[SPLIT * NCH * ZROW];  // 4 MB partial sums

// ---------------------------------------------------------------------------
// Kernel 1: build per-channel ordered row lists. One block, 32 warps; warp w
// owns channel w. ids staged through shared memory so global loads are
// coalesced & parallel; the ballot loop then runs on LDS latency only.
// dtype probe: ch_ids may be int32 or int64 (JAX x64 flag). Interpret as
// int32[]; if the first 64 odd words are all zero it's int64 (values < 32).
// ---------------------------------------------------------------------------
__global__ void __launch_bounds__(1024, 1)
build_lists_kernel(const int* __restrict__ ids32) {
    __shared__ int sid[BATCH];         // 16 KB
    __shared__ int s_stride;
    if (threadIdx.x == 0) {
        int nz = 0;
        #pragma unroll
        for (int i = 0; i < 64; ++i) nz += (ids32[2 * i + 1] != 0);
        s_stride = (nz == 0) ? 2 : 1;
    }
    __syncthreads();
    const int stride = s_stride;
    for (int i = threadIdx.x; i < BATCH; i += 1024) sid[i] = ids32[i * stride];
    __syncthreads();

    const int w    = threadIdx.x >> 5;
    const int lane = threadIdx.x & 31;
    int count = 0;
    #pragma unroll 4
    for (int base = 0; base < BATCH; base += 32) {
        const int id = sid[base + lane];
        const unsigned mask = __ballot_sync(0xffffffffu, id == w);
        if (id == w) {
            const int pos = count + __popc(mask & ((1u << lane) - 1u));
            g_list[w * BATCH + pos] = base + lane;
        }
        count += __popc(mask);
    }
    if (lane == 0) g_counts[w] = count;
}

// ---------------------------------------------------------------------------
// Kernel 2: top-half copy + partial channel sums.
// grid = (NCHUNK, NCH, SPLIT), block = 128. Block (chunk, c, s) handles rows
// i = s, s+SPLIT, ... of channel c: copies their z slice to the top half of
// out and accumulates a partial sum, stored to g_partial (fixed order ->
// deterministic).
// ---------------------------------------------------------------------------
__global__ void __launch_bounds__(128)
sum_copy_kernel(const float* __restrict__ z, float* __restrict__ out) {
    __shared__ int rows[BATCH / SPLIT + 4];   // worst case 1024 entries

    const int chunk = blockIdx.x;
    const int c     = blockIdx.y;
    const int s     = blockIdx.z;
    const int tid   = threadIdx.x;

    const int cnt = g_counts[c];
    // my rows: indices s, s+SPLIT, ... < cnt
    const int m = (cnt > s) ? (cnt - s + SPLIT - 1) / SPLIT : 0;
    for (int i = tid; i < m; i += 128)
        rows[i] = g_list[c * BATCH + s + i * SPLIT];
    __syncthreads();

    const int off = chunk * CHUNK + tid * 4;

    float4 acc = make_float4(0.f, 0.f, 0.f, 0.f);
    int i = 0;
    for (; i + 4 <= m; i += 4) {
        const int b0 = rows[i + 0], b1 = rows[i + 1];
        const int b2 = rows[i + 2], b3 = rows[i + 3];
        const float4 v0 = *(const float4*)(z + (size_t)b0 * ZROW + off);
        const float4 v1 = *(const float4*)(z + (size_t)b1 * ZROW + off);
        const float4 v2 = *(const float4*)(z + (size_t)b2 * ZROW + off);
        const float4 v3 = *(const float4*)(z + (size_t)b3 * ZROW + off);
        *(float4*)(out + (size_t)b0 * OROW + off) = v0;
        *(float4*)(out + (size_t)b1 * OROW + off) = v1;
        *(float4*)(out + (size_t)b2 * OROW + off) = v2;
        *(float4*)(out + (size_t)b3 * OROW + off) = v3;
        acc.x += (v0.x + v1.x) + (v2.x + v3.x);
        acc.y += (v0.y + v1.y) + (v2.y + v3.y);
        acc.z += (v0.z + v1.z) + (v2.z + v3.z);
        acc.w += (v0.w + v1.w) + (v2.w + v3.w);
    }
    for (; i < m; ++i) {
        const int b = rows[i];
        const float4 v = *(const float4*)(z + (size_t)b * ZROW + off);
        *(float4*)(out + (size_t)b * OROW + off) = v;
        acc.x += v.x; acc.y += v.y; acc.z += v.z; acc.w += v.w;
    }

    *(float4*)(g_partial + ((size_t)s * NCH + c) * ZROW + off) = acc;
}

// ---------------------------------------------------------------------------
// Kernel 3: combine partials -> mean, broadcast to bottom half.
// grid = (NCHUNK, NCH, SPLIT), block = 128. Block (chunk, c, s) writes the
// bottom-half slice for rows s::SPLIT of channel c.
// ---------------------------------------------------------------------------
__global__ void __launch_bounds__(128)
broadcast_kernel(float* __restrict__ out) {
    __shared__ int rows[BATCH / SPLIT + 4];

    const int chunk = blockIdx.x;
    const int c     = blockIdx.y;
    const int s     = blockIdx.z;
    const int tid   = threadIdx.x;

    const int cnt = g_counts[c];
    const int m = (cnt > s) ? (cnt - s + SPLIT - 1) / SPLIT : 0;
    for (int i = tid; i < m; i += 128)
        rows[i] = g_list[c * BATCH + s + i * SPLIT];
    __syncthreads();
    if (m == 0) return;

    const int off = chunk * CHUNK + tid * 4;

    float4 acc = make_float4(0.f, 0.f, 0.f, 0.f);
    #pragma unroll
    for (int p = 0; p < SPLIT; ++p) {
        const float4 v = *(const float4*)(g_partial + ((size_t)p * NCH + c) * ZROW + off);
        acc.x += v.x; acc.y += v.y; acc.z += v.z; acc.w += v.w;
    }
    const float inv = 1.0f / (float)(cnt > 0 ? cnt : 1);
    float4 mn;
    mn.x = acc.x * inv; mn.y = acc.y * inv; mn.z = acc.z * inv; mn.w = acc.w * inv;

    int j = 0;
    for (; j + 4 <= m; j += 4) {
        *(float4*)(out + (size_t)rows[j + 0] * OROW + ZROW + off) = mn;
        *(float4*)(out + (size_t)rows[j + 1] * OROW + ZROW + off) = mn;
        *(float4*)(out + (size_t)rows[j + 2] * OROW + ZROW + off) = mn;
        *(float4*)(out + (size_t)rows[j + 3] * OROW + ZROW + off) = mn;
    }
    for (; j < m; ++j)
        *(float4*)(out + (size_t)rows[j] * OROW + ZROW + off) = mn;
}

extern "C" void kernel_launch(void* const* d_in, const int* in_sizes, int n_in,
                              void* d_out, int out_size) {
    const float* z   = (const float*)d_in[0];
    const int*   ids = (const int*)d_in[1];
    float*       out = (float*)d_out;

    build_lists_kernel<<<1, 1024>>>(ids);

    dim3 grid(NCHUNK, NCH, SPLIT);
    sum_copy_kernel<<<grid, 128>>>(z, out);
    broadcast_kernel<<<grid, 128>>>(out);
}

// round 4
// speedup vs baseline: 1.2299x; 1.0515x over previous
#include <cuda_runtime.h>

// Problem shape (fixed by the dataset):
//   z:      (4096, 1, 64, 128) f32  -> row of 8192 floats per batch entry
//   ch_ids: (4096,) int32 or int64, values in [0, 32)
//   out:    (4096, 128, 128) f32    -> first 8192 = z row, last 8192 = channel mean
#define BATCH   4096
#define NCH     32
#define NSEG    32                     // segments of 128 ids, one warp each
#define SEGLEN  (BATCH / NSEG)         // 128
#define ZROW    8192
#define OROW    16384
#define CHUNK   512                    // floats per block slice (128 thr * float4)
#define NCHUNK  (ZROW / CHUNK)         // 16
#define SPLIT   4                      // row-list split factor per channel

// Scratch (no allocations allowed):
__device__ int   g_list[NCH * BATCH];            // per-channel ordered rows
__device__ int   g_counts[NCH];
__device__ float g_partial[SPLIT * NCH * ZROW];  // 4 MB partial sums

// ---------------------------------------------------------------------------
// Kernel 1: build per-channel ordered row lists via __match_any_sync.
// One block, 1024 threads = 32 warps; warp w owns segment w (128 ids).
// Phase A: 4 match iterations -> per-element local rank + per-(seg,ch) counts.
// Phase B: per-channel shfl prefix scan over segments -> global offsets.
// Phase C: scatter b into g_list at offs[seg][ch] + local_pos. Stable b-order,
// deterministic, no atomics.
// dtype probe: ch_ids may be int32 or int64 (JAX x64 flag). Interpret as
// int32[]; if the first 64 odd words are all zero it's int64 (values < 32).
// ---------------------------------------------------------------------------
__global__ void __launch_bounds__(1024, 1)
build_lists_kernel(const int* __restrict__ ids32) {
    __shared__ int sid[BATCH];               // 16 KB
    __shared__ unsigned short posl[BATCH];   // 8 KB: local position within segment
    __shared__ int seg_count[NSEG][NCH + 1]; // padded vs bank conflicts
    __shared__ int offs[NSEG][NCH + 1];      // exclusive prefix per channel
    __shared__ int s_high_nz;

    const int tid  = threadIdx.x;
    const int w    = tid >> 5;               // warp == segment (and channel in B)
    const int lane = tid & 31;

    if (tid == 0) s_high_nz = 0;
    __syncthreads();
    if (tid < 64) {
        if (ids32[2 * tid + 1] != 0) atomicAdd(&s_high_nz, 1);
    }
    __syncthreads();
    const int stride = (s_high_nz == 0) ? 2 : 1;

    for (int i = tid; i < BATCH; i += 1024) sid[i] = ids32[i * stride];
    if (lane < NCH) seg_count[w][lane] = 0;
    __syncthreads();

    // Phase A: per-segment local positions (4 iterations of 32 ids)
    #pragma unroll
    for (int it = 0; it < 4; ++it) {
        const int idx = w * SEGLEN + it * 32 + lane;
        const int id  = sid[idx];
        const unsigned mm   = __match_any_sync(0xffffffffu, id);
        const int      rank = __popc(mm & ((1u << lane) - 1u));
        const int      base = seg_count[w][id];   // broadcast within match group
        posl[idx] = (unsigned short)(base + rank);
        if (((mm >> lane) & 1u) && rank == 0)     // group leader
            seg_count[w][id] = base + __popc(mm);
        __syncwarp();
    }
    __syncthreads();

    // Phase B: warp c scans channel c across 32 segments (lane = segment)
    {
        const int c = w;
        int v = seg_count[lane][c];
        int incl = v;
        #pragma unroll
        for (int d = 1; d < 32; d <<= 1) {
            const int t = __shfl_up_sync(0xffffffffu, incl, d);
            if (lane >= d) incl += t;
        }
        offs[lane][c] = incl - v;                // exclusive prefix
        if (lane == 31) g_counts[c] = incl;      // total
    }
    __syncthreads();

    // Phase C: scatter
    #pragma unroll
    for (int it = 0; it < 4; ++it) {
        const int idx = w * SEGLEN + it * 32 + lane;
        const int id  = sid[idx];
        g_list[id * BATCH + offs[w][id] + (int)posl[idx]] = idx;
    }
}

// ---------------------------------------------------------------------------
// Kernel 2: top-half copy + partial channel sums.
// grid = (NCHUNK, NCH, SPLIT), block = 128. Block (chunk, c, s) handles rows
// i = s, s+SPLIT, ... of channel c: copies their z slice to the top half of
// out and accumulates a partial sum into g_partial (fixed order, deterministic).
// ---------------------------------------------------------------------------
__global__ void __launch_bounds__(128)
sum_copy_kernel(const float* __restrict__ z, float* __restrict__ out) {
    __shared__ int rows[BATCH / SPLIT + 4];

    const int chunk = blockIdx.x;
    const int c     = blockIdx.y;
    const int s     = blockIdx.z;
    const int tid   = threadIdx.x;

    const int cnt = g_counts[c];
    const int m = (cnt > s) ? (cnt - s + SPLIT - 1) / SPLIT : 0;
    for (int i = tid; i < m; i += 128)
        rows[i] = g_list[c * BATCH + s + i * SPLIT];
    __syncthreads();

    const int off = chunk * CHUNK + tid * 4;

    float4 acc = make_float4(0.f, 0.f, 0.f, 0.f);
    int i = 0;
    for (; i + 4 <= m; i += 4) {
        const int b0 = rows[i + 0], b1 = rows[i + 1];
        const int b2 = rows[i + 2], b3 = rows[i + 3];
        const float4 v0 = *(const float4*)(z + (size_t)b0 * ZROW + off);
        const float4 v1 = *(const float4*)(z + (size_t)b1 * ZROW + off);
        const float4 v2 = *(const float4*)(z + (size_t)b2 * ZROW + off);
        const float4 v3 = *(const float4*)(z + (size_t)b3 * ZROW + off);
        *(float4*)(out + (size_t)b0 * OROW + off) = v0;
        *(float4*)(out + (size_t)b1 * OROW + off) = v1;
        *(float4*)(out + (size_t)b2 * OROW + off) = v2;
        *(float4*)(out + (size_t)b3 * OROW + off) = v3;
        acc.x += (v0.x + v1.x) + (v2.x + v3.x);
        acc.y += (v0.y + v1.y) + (v2.y + v3.y);
        acc.z += (v0.z + v1.z) + (v2.z + v3.z);
        acc.w += (v0.w + v1.w) + (v2.w + v3.w);
    }
    for (; i < m; ++i) {
        const int b = rows[i];
        const float4 v = *(const float4*)(z + (size_t)b * ZROW + off);
        *(float4*)(out + (size_t)b * OROW + off) = v;
        acc.x += v.x; acc.y += v.y; acc.z += v.z; acc.w += v.w;
    }

    *(float4*)(g_partial + ((size_t)s * NCH + c) * ZROW + off) = acc;
}

// ---------------------------------------------------------------------------
// Kernel 3: combine partials -> mean, broadcast to bottom half.
// grid = (NCHUNK, NCH, SPLIT), block = 128.
// ---------------------------------------------------------------------------
__global__ void __launch_bounds__(128)
broadcast_kernel(float* __restrict__ out) {
    __shared__ int rows[BATCH / SPLIT + 4];

    const int chunk = blockIdx.x;
    const int c     = blockIdx.y;
    const int s     = blockIdx.z;
    const int tid   = threadIdx.x;

    const int cnt = g_counts[c];
    const int m = (cnt > s) ? (cnt - s + SPLIT - 1) / SPLIT : 0;
    for (int i = tid; i < m; i += 128)
        rows[i] = g_list[c * BATCH + s + i * SPLIT];
    __syncthreads();
    if (m == 0) return;

    const int off = chunk * CHUNK + tid * 4;

    float4 acc = make_float4(0.f, 0.f, 0.f, 0.f);
    #pragma unroll
    for (int p = 0; p < SPLIT; ++p) {
        const float4 v = *(const float4*)(g_partial + ((size_t)p * NCH + c) * ZROW + off);
        acc.x += v.x; acc.y += v.y; acc.z += v.z; acc.w += v.w;
    }
    const float inv = 1.0f / (float)(cnt > 0 ? cnt : 1);
    float4 mn;
    mn.x = acc.x * inv; mn.y = acc.y * inv; mn.z = acc.z * inv; mn.w = acc.w * inv;

    int j = 0;
    for (; j + 4 <= m; j += 4) {
        *(float4*)(out + (size_t)rows[j + 0] * OROW + ZROW + off) = mn;
        *(float4*)(out + (size_t)rows[j + 1] * OROW + ZROW + off) = mn;
        *(float4*)(out + (size_t)rows[j + 2] * OROW + ZROW + off) = mn;
        *(float4*)(out + (size_t)rows[j + 3] * OROW + ZROW + off) = mn;
    }
    for (; j < m; ++j)
        *(float4*)(out + (size_t)rows[j] * OROW + ZROW + off) = mn;
}

extern "C" void kernel_launch(void* const* d_in, const int* in_sizes, int n_in,
                              void* d_out, int out_size) {
    const float* z   = (const float*)d_in[0];
    const int*   ids = (const int*)d_in[1];
    float*       out = (float*)d_out;

    build_lists_kernel<<<1, 1024>>>(ids);

    dim3 grid(NCHUNK, NCH, SPLIT);
    sum_copy_kernel<<<grid, 128>>>(z, out);
    broadcast_kernel<<<grid, 128>>>(out);
}

// round 5
// speedup vs baseline: 1.2644x; 1.0281x over previous
#include <cuda_runtime.h>

// Problem shape (fixed by the dataset):
//   z:      (4096, 1, 64, 128) f32  -> row of 8192 floats per batch entry
//   ch_ids: (4096,) int32 or int64, values in [0, 32)
//   out:    (4096, 128, 128) f32    -> first 8192 = z row, last 8192 = channel mean
#define BATCH   4096
#define NCH     32
#define ZROW    8192
#define OROW    16384
#define NTHR    256
#define CHUNK   1024                   // floats per block slice (256 thr * float4)
#define NCHUNK  (ZROW / CHUNK)         // 8
#define SPLIT   4                      // contiguous batch quarters
#define RANGE   (BATCH / SPLIT)        // 1024 rows per quarter

// Scratch (no allocations allowed):
__device__ float g_partial[SPLIT * NCH * ZROW];  // 4 MB partial sums
__device__ int   g_pcnt[SPLIT * NCH];            // per-(quarter, channel) counts

// ---------------------------------------------------------------------------
// Per-block row-list builder: scan quarter s's 1024 ids, keep rows with
// id == c, in fixed (segment, ballot) order -> deterministic. All 256 threads
// participate; returns the count. ~4 ballot rounds per warp, ids prefetched
// into registers so ballots never wait on memory.
// dtype probe: ch_ids may be int32 or int64 (JAX x64 flag). Interpret as
// int32[]; if the first 128 odd words are all zero it's int64 (values < 32).
// ---------------------------------------------------------------------------
__device__ __forceinline__ int build_rows(const int* __restrict__ ids32,
                                          int c, int s, int* rows, int tid) {
    const int lane = tid & 31;
    const int w    = tid >> 5;                 // 8 warps

    // stride probe (warp-uniform, every warp computes the same answer)
    int stride;
    {
        const int x = ids32[2 * lane + 1] | ids32[2 * (lane + 32) + 1];
        const unsigned nz = __ballot_sync(0xffffffffu, x != 0);
        stride = (nz == 0) ? 2 : 1;
    }

    // warp w covers rows [s*RANGE + w*128, +128): prefetch 4 ids per lane
    const int base = s * RANGE + w * 128;
    int myid[4];
    #pragma unroll
    for (int r = 0; r < 4; ++r)
        myid[r] = ids32[(base + r * 32 + lane) * stride];

    __shared__ int segcnt[9];
    __shared__ int segoff[8];

    unsigned mk[4];
    int      lp[4];
    int count = 0;
    #pragma unroll
    for (int r = 0; r < 4; ++r) {
        mk[r] = __ballot_sync(0xffffffffu, myid[r] == c);
        lp[r] = count + __popc(mk[r] & ((1u << lane) - 1u));
        count += __popc(mk[r]);
    }
    if (lane == 0) segcnt[w] = count;
    __syncthreads();

    if (w == 0) {                              // prefix over 8 segments
        int v = (lane < 8) ? segcnt[lane] : 0;
        int incl = v;
        #pragma unroll
        for (int d = 1; d < 8; d <<= 1) {
            const int t = __shfl_up_sync(0xffffffffu, incl, d);
            if (lane >= d) incl += t;
        }
        if (lane < 8) segoff[lane] = incl - v;
        if (lane == 7) segcnt[8] = incl;       // total
    }
    __syncthreads();

    const int off = segoff[w];
    #pragma unroll
    for (int r = 0; r < 4; ++r)
        if ((mk[r] >> lane) & 1u)
            rows[off + lp[r]] = base + r * 32 + lane;
    const int total = segcnt[8];
    __syncthreads();                           // rows visible to all
    return total;
}

// ---------------------------------------------------------------------------
// Kernel A: top-half copy + per-quarter partial channel sums + counts.
// grid = (NCHUNK, NCH, SPLIT), block = 256.
// ---------------------------------------------------------------------------
__global__ void __launch_bounds__(NTHR)
sum_copy_kernel(const float* __restrict__ z, float* __restrict__ out,
                const int* __restrict__ ids) {
    __shared__ int rows[RANGE];

    const int chunk = blockIdx.x;
    const int c     = blockIdx.y;
    const int s     = blockIdx.z;
    const int tid   = threadIdx.x;

    const int m = build_rows(ids, c, s, rows, tid);
    const int off = chunk * CHUNK + tid * 4;

    float4 acc = make_float4(0.f, 0.f, 0.f, 0.f);
    int i = 0;
    for (; i + 4 <= m; i += 4) {
        const int b0 = rows[i + 0], b1 = rows[i + 1];
        const int b2 = rows[i + 2], b3 = rows[i + 3];
        const float4 v0 = *(const float4*)(z + (size_t)b0 * ZROW + off);
        const float4 v1 = *(const float4*)(z + (size_t)b1 * ZROW + off);
        const float4 v2 = *(const float4*)(z + (size_t)b2 * ZROW + off);
        const float4 v3 = *(const float4*)(z + (size_t)b3 * ZROW + off);
        *(float4*)(out + (size_t)b0 * OROW + off) = v0;
        *(float4*)(out + (size_t)b1 * OROW + off) = v1;
        *(float4*)(out + (size_t)b2 * OROW + off) = v2;
        *(float4*)(out + (size_t)b3 * OROW + off) = v3;
        acc.x += (v0.x + v1.x) + (v2.x + v3.x);
        acc.y += (v0.y + v1.y) + (v2.y + v3.y);
        acc.z += (v0.z + v1.z) + (v2.z + v3.z);
        acc.w += (v0.w + v1.w) + (v2.w + v3.w);
    }
    for (; i < m; ++i) {
        const int b = rows[i];
        const float4 v = *(const float4*)(z + (size_t)b * ZROW + off);
        *(float4*)(out + (size_t)b * OROW + off) = v;
        acc.x += v.x; acc.y += v.y; acc.z += v.z; acc.w += v.w;
    }

    *(float4*)(g_partial + ((size_t)s * NCH + c) * ZROW + off) = acc;
    if (tid == 0 && chunk == 0) g_pcnt[s * NCH + c] = m;
}

// ---------------------------------------------------------------------------
// Kernel B: combine partials -> mean, broadcast to bottom half.
// grid = (NCHUNK, NCH, SPLIT), block = 256. Same scan -> same partition.
// ---------------------------------------------------------------------------
__global__ void __launch_bounds__(NTHR)
broadcast_kernel(float* __restrict__ out, const int* __restrict__ ids) {
    __shared__ int rows[RANGE];

    const int chunk = blockIdx.x;
    const int c     = blockIdx.y;
    const int s     = blockIdx.z;
    const int tid   = threadIdx.x;

    const int m = build_rows(ids, c, s, rows, tid);
    if (m == 0) return;

    const int off = chunk * CHUNK + tid * 4;

    int cnt = 0;
    #pragma unroll
    for (int p = 0; p < SPLIT; ++p) cnt += g_pcnt[p * NCH + c];

    float4 acc = make_float4(0.f, 0.f, 0.f, 0.f);
    #pragma unroll
    for (int p = 0; p < SPLIT; ++p) {
        const float4 v = *(const float4*)(g_partial + ((size_t)p * NCH + c) * ZROW + off);
        acc.x += v.x; acc.y += v.y; acc.z += v.z; acc.w += v.w;
    }
    const float inv = 1.0f / (float)(cnt > 0 ? cnt : 1);
    float4 mn;
    mn.x = acc.x * inv; mn.y = acc.y * inv; mn.z = acc.z * inv; mn.w = acc.w * inv;

    int j = 0;
    for (; j + 4 <= m; j += 4) {
        *(float4*)(out + (size_t)rows[j + 0] * OROW + ZROW + off) = mn;
        *(float4*)(out + (size_t)rows[j + 1] * OROW + ZROW + off) = mn;
        *(float4*)(out + (size_t)rows[j + 2] * OROW + ZROW + off) = mn;
        *(float4*)(out + (size_t)rows[j + 3] * OROW + ZROW + off) = mn;
    }
    for (; j < m; ++j)
        *(float4*)(out + (size_t)rows[j] * OROW + ZROW + off) = mn;
}

extern "C" void kernel_launch(void* const* d_in, const int* in_sizes, int n_in,
                              void* d_out, int out_size) {
    const float* z   = (const float*)d_in[0];
    const int*   ids = (const int*)d_in[1];
    float*       out = (float*)d_out;

    dim3 grid(NCHUNK, NCH, SPLIT);
    sum_copy_kernel<<<grid, NTHR>>>(z, out, ids);
    broadcast_kernel<<<grid, NTHR>>>(out, ids);
}

// round 6
// speedup vs baseline: 1.3179x; 1.0422x over previous
#include <cuda_runtime.h>

// Problem shape (fixed by the dataset):
//   z:      (4096, 1, 64, 128) f32  -> row of 8192 floats per batch entry
//   ch_ids: (4096,) int32 or int64, values in [0, 32)
//   out:    (4096, 128, 128) f32    -> first 8192 = z row, last 8192 = channel mean
#define BATCH   4096
#define NCH     32
#define ZROW    8192
#define OROW    16384
#define NTHR    512                    // 4 row-groups x 128 lanes
#define NGRP    4
#define CHUNK   512                    // floats per block slice (128 lanes * float4)
#define NCHUNK  (ZROW / CHUNK)         // 16

// ---------------------------------------------------------------------------
// Build the row list for channel c by scanning all 4096 ids with 16 warps
// (8 ballot rounds each, ids prefetched to registers). Fixed (warp, round,
// lane) order -> deterministic. Returns total count.
// dtype probe: ch_ids may be int32 or int64 (JAX x64 flag). Interpret as
// int32[]; if the first 128 odd words are all zero it's int64 (values < 32).
// ---------------------------------------------------------------------------
__device__ __forceinline__ int build_rows_full(const int* __restrict__ ids32,
                                               int c, int* rows, int tid) {
    __shared__ int segcnt[17];
    __shared__ int segoff[16];

    const int lane = tid & 31;
    const int w    = tid >> 5;                 // 16 warps

    int stride;                                // warp-uniform probe
    {
        const int x = ids32[2 * lane + 1] | ids32[2 * (lane + 32) + 1];
        const unsigned nz = __ballot_sync(0xffffffffu, x != 0);
        stride = (nz == 0) ? 2 : 1;
    }

    const int base = w * 256;                  // warp covers 256 ids
    int myid[8];
    #pragma unroll
    for (int r = 0; r < 8; ++r)
        myid[r] = ids32[(base + r * 32 + lane) * stride];

    unsigned mk[8];
    int      lp[8];
    int count = 0;
    #pragma unroll
    for (int r = 0; r < 8; ++r) {
        mk[r] = __ballot_sync(0xffffffffu, myid[r] == c);
        lp[r] = count + __popc(mk[r] & ((1u << lane) - 1u));
        count += __popc(mk[r]);
    }
    if (lane == 0) segcnt[w] = count;
    __syncthreads();

    if (w == 0) {                              // prefix over 16 warp-segments
        int v = (lane < 16) ? segcnt[lane] : 0;
        int incl = v;
        #pragma unroll
        for (int d = 1; d < 16; d <<= 1) {
            const int t = __shfl_up_sync(0xffffffffu, incl, d);
            if (lane >= d) incl += t;
        }
        if (lane < 16) segoff[lane] = incl - v;
        if (lane == 15) segcnt[16] = incl;
    }
    __syncthreads();

    const int off = segoff[w];
    #pragma unroll
    for (int r = 0; r < 8; ++r)
        if ((mk[r] >> lane) & 1u)
            rows[off + lp[r]] = base + r * 32 + lane;
    const int total = segcnt[16];
    __syncthreads();
    return total;
}

// ---------------------------------------------------------------------------
// Single fused kernel. grid = (NCHUNK, NCH), block = 512.
// Group g (128 lanes) handles rows g, g+4, ... of channel c:
//   phase 2: load z slice, write top-half copy, accumulate partial sum
//   phase 3: smem reduce across the 4 groups (fixed order) -> channel mean
//   phase 4: write bottom-half mean slice for the same rows
// ---------------------------------------------------------------------------
__global__ void __launch_bounds__(NTHR, 3)
mix_kernel(const float* __restrict__ z, float* __restrict__ out,
           const int* __restrict__ ids) {
    __shared__ int    rows[BATCH];       // 16 KB (worst case one channel owns all)
    __shared__ float4 red[NGRP][128];    // 8 KB cross-group reduce

    const int chunk = blockIdx.x;
    const int c     = blockIdx.y;
    const int tid   = threadIdx.x;

    const int m = build_rows_full(ids, c, rows, tid);

    const int g   = tid >> 7;            // row-group 0..3
    const int l   = tid & 127;           // lane within group
    const int off = chunk * CHUNK + l * 4;

    // phase 2: copy + partial accumulate (rows g, g+4, ...)
    const int nb = (m > g) ? (m - g + NGRP - 1) / NGRP : 0;
    float4 acc = make_float4(0.f, 0.f, 0.f, 0.f);
    int j = 0;
    for (; j + 4 <= nb; j += 4) {
        const int b0 = rows[g + NGRP * (j + 0)];
        const int b1 = rows[g + NGRP * (j + 1)];
        const int b2 = rows[g + NGRP * (j + 2)];
        const int b3 = rows[g + NGRP * (j + 3)];
        const float4 v0 = *(const float4*)(z + (size_t)b0 * ZROW + off);
        const float4 v1 = *(const float4*)(z + (size_t)b1 * ZROW + off);
        const float4 v2 = *(const float4*)(z + (size_t)b2 * ZROW + off);
        const float4 v3 = *(const float4*)(z + (size_t)b3 * ZROW + off);
        *(float4*)(out + (size_t)b0 * OROW + off) = v0;
        *(float4*)(out + (size_t)b1 * OROW + off) = v1;
        *(float4*)(out + (size_t)b2 * OROW + off) = v2;
        *(float4*)(out + (size_t)b3 * OROW + off) = v3;
        acc.x += (v0.x + v1.x) + (v2.x + v3.x);
        acc.y += (v0.y + v1.y) + (v2.y + v3.y);
        acc.z += (v0.z + v1.z) + (v2.z + v3.z);
        acc.w += (v0.w + v1.w) + (v2.w + v3.w);
    }
    for (; j < nb; ++j) {
        const int b = rows[g + NGRP * j];
        const float4 v = *(const float4*)(z + (size_t)b * ZROW + off);
        *(float4*)(out + (size_t)b * OROW + off) = v;
        acc.x += v.x; acc.y += v.y; acc.z += v.z; acc.w += v.w;
    }

    // phase 3: cross-group reduce (deterministic fixed order)
    red[g][l] = acc;
    __syncthreads();
    const float4 p0 = red[0][l];
    const float4 p1 = red[1][l];
    const float4 p2 = red[2][l];
    const float4 p3 = red[3][l];
    const float inv = 1.0f / (float)(m > 0 ? m : 1);
    float4 mn;
    mn.x = ((p0.x + p1.x) + (p2.x + p3.x)) * inv;
    mn.y = ((p0.y + p1.y) + (p2.y + p3.y)) * inv;
    mn.z = ((p0.z + p1.z) + (p2.z + p3.z)) * inv;
    mn.w = ((p0.w + p1.w) + (p2.w + p3.w)) * inv;

    // phase 4: broadcast mean slice to bottom half of the same rows
    j = 0;
    for (; j + 4 <= nb; j += 4) {
        *(float4*)(out + (size_t)rows[g + NGRP * (j + 0)] * OROW + ZROW + off) = mn;
        *(float4*)(out + (size_t)rows[g + NGRP * (j + 1)] * OROW + ZROW + off) = mn;
        *(float4*)(out + (size_t)rows[g + NGRP * (j + 2)] * OROW + ZROW + off) = mn;
        *(float4*)(out + (size_t)rows[g + NGRP * (j + 3)] * OROW + ZROW + off) = mn;
    }
    for (; j < nb; ++j)
        *(float4*)(out + (size_t)rows[g + NGRP * j] * OROW + ZROW + off) = mn;
}

extern "C" void kernel_launch(void* const* d_in, const int* in_sizes, int n_in,
                              void* d_out, int out_size) {
    const float* z   = (const float*)d_in[0];
    const int*   ids = (const int*)d_in[1];
    float*       out = (float*)d_out;

    dim3 grid(NCHUNK, NCH);
    mix_kernel<<<grid, NTHR>>>(z, out, ids);
}